// round 1
// baseline (speedup 1.0000x reference)
#include <cuda_runtime.h>
#include <cuda_bf16.h>
#include <math.h>

// Problem constants (fixed shapes for this problem instance)
#define D        512
#define TOTAL    4096
#define NPAIRS   2048
#define INV_T    (1.0f / 0.07f)

#define BM 128
#define BN 128
#define BK 32

// ---- device scratch (no allocations allowed) ----
__device__ float  g_norm[TOTAL * D];   // normalized embeddings, fp32
__device__ float  g_pos[NPAIRS];       // positive-pair logits S_p
__device__ double g_neg;               // masked exp-sum accumulator

// ---------------------------------------------------------------------------
// 1) Row L2-normalize. One block (128 threads) per row; each thread owns one
//    float4. Block 0 / thread 0 also zeroes the neg accumulator (runs before
//    the GEMM kernel in stream order).
// ---------------------------------------------------------------------------
__global__ void normalize_kernel(const float* __restrict__ E) {
    int row = blockIdx.x;
    int tid = threadIdx.x;

    if (row == 0 && tid == 0) g_neg = 0.0;

    const float4* src = reinterpret_cast<const float4*>(E + (size_t)row * D);
    float4 v = src[tid];
    float ss = v.x * v.x + v.y * v.y + v.z * v.z + v.w * v.w;

    // reduce 128 threads
    #pragma unroll
    for (int off = 16; off > 0; off >>= 1)
        ss += __shfl_down_sync(0xffffffffu, ss, off);

    __shared__ float wsum[4];
    if ((tid & 31) == 0) wsum[tid >> 5] = ss;
    __syncthreads();
    float total = wsum[0] + wsum[1] + wsum[2] + wsum[3];
    float inv = rsqrtf(total);

    float4 o;
    o.x = v.x * inv; o.y = v.y * inv; o.z = v.z * inv; o.w = v.w * inv;
    reinterpret_cast<float4*>(g_norm + (size_t)row * D)[tid] = o;
}

// ---------------------------------------------------------------------------
// 2) Tiled SGEMM over upper-triangular tiles with fused masked exp-sum.
//    Tile (bi,bj), bj>=bi. Off-diagonal tiles: all (i,j) have i<j. Diagonal
//    tiles: predicate i<j. Label mask: labels[i>>1] != labels[j>>1].
// ---------------------------------------------------------------------------
__global__ void __launch_bounds__(256) gemm_negsum_kernel(const int* __restrict__ labels) {
    int bi = blockIdx.y, bj = blockIdx.x;
    if (bj < bi) return;

    __shared__ float As[BK][BM + 4];
    __shared__ float Bs[BK][BN + 4];
    __shared__ int   labR[BM];
    __shared__ int   labC[BN];

    int tid = threadIdx.x;
    int tx = tid & 15;       // 0..15 -> column group
    int ty = tid >> 4;       // 0..15 -> row group
    int row0 = bi * BM;
    int col0 = bj * BN;

    if (tid < 128) {
        labR[tid] = labels[(row0 + tid) >> 1];
        labC[tid] = labels[(col0 + tid) >> 1];
    }

    float acc[8][8];
    #pragma unroll
    for (int i = 0; i < 8; i++)
        #pragma unroll
        for (int j = 0; j < 8; j++) acc[i][j] = 0.0f;

    for (int k0 = 0; k0 < D; k0 += BK) {
        // load 128x32 fp32 tiles of A (rows) and B (cols), transposed into smem
        #pragma unroll
        for (int it = 0; it < 4; it++) {
            int li = tid + it * 256;          // 0..1023 float4 slots
            int r  = li >> 3;                 // row within tile
            int c4 = li & 7;                  // float4 index within 32-wide K slab
            float4 va = *reinterpret_cast<const float4*>(
                &g_norm[(size_t)(row0 + r) * D + k0 + c4 * 4]);
            As[c4 * 4 + 0][r] = va.x;
            As[c4 * 4 + 1][r] = va.y;
            As[c4 * 4 + 2][r] = va.z;
            As[c4 * 4 + 3][r] = va.w;
            float4 vb = *reinterpret_cast<const float4*>(
                &g_norm[(size_t)(col0 + r) * D + k0 + c4 * 4]);
            Bs[c4 * 4 + 0][r] = vb.x;
            Bs[c4 * 4 + 1][r] = vb.y;
            Bs[c4 * 4 + 2][r] = vb.z;
            Bs[c4 * 4 + 3][r] = vb.w;
        }
        __syncthreads();

        #pragma unroll 8
        for (int k = 0; k < BK; k++) {
            float ra[8], rb[8];
            #pragma unroll
            for (int i = 0; i < 8; i++) ra[i] = As[k][ty * 8 + i];
            #pragma unroll
            for (int j = 0; j < 8; j++) rb[j] = Bs[k][tx * 8 + j];
            #pragma unroll
            for (int i = 0; i < 8; i++)
                #pragma unroll
                for (int j = 0; j < 8; j++)
                    acc[i][j] = fmaf(ra[i], rb[j], acc[i][j]);
        }
        __syncthreads();
    }

    // epilogue: masked exp-sum
    bool diag = (bi == bj);
    float lsum = 0.0f;
    #pragma unroll
    for (int i = 0; i < 8; i++) {
        int gi = ty * 8 + i;
        int li = labR[gi];
        int rowg = row0 + gi;
        #pragma unroll
        for (int j = 0; j < 8; j++) {
            int gj = tx * 8 + j;
            bool ok = (li != labC[gj]) && (!diag || (rowg < col0 + gj));
            if (ok) lsum += __expf(acc[i][j] * INV_T);
        }
    }

    // block reduce -> double atomic
    #pragma unroll
    for (int off = 16; off > 0; off >>= 1)
        lsum += __shfl_down_sync(0xffffffffu, lsum, off);
    __shared__ float red[8];
    if ((tid & 31) == 0) red[tid >> 5] = lsum;
    __syncthreads();
    if (tid == 0) {
        float s = 0.0f;
        #pragma unroll
        for (int w = 0; w < 8; w++) s += red[w];
        atomicAdd(&g_neg, (double)s);
    }
}

// ---------------------------------------------------------------------------
// 3) Positive-pair logits: one warp per pair (2k, 2k+1).
// ---------------------------------------------------------------------------
__global__ void pos_kernel() {
    int gthread = blockIdx.x * blockDim.x + threadIdx.x;
    int pair = gthread >> 5;
    int lane = threadIdx.x & 31;
    if (pair >= NPAIRS) return;

    const float4* a = reinterpret_cast<const float4*>(g_norm + (size_t)(2 * pair) * D);
    const float4* b = reinterpret_cast<const float4*>(g_norm + (size_t)(2 * pair + 1) * D);
    float d = 0.0f;
    #pragma unroll
    for (int i = lane; i < D / 4; i += 32) {
        float4 x = a[i], y = b[i];
        d += x.x * y.x + x.y * y.y + x.z * y.z + x.w * y.w;
    }
    #pragma unroll
    for (int off = 16; off > 0; off >>= 1)
        d += __shfl_down_sync(0xffffffffu, d, off);
    if (lane == 0) g_pos[pair] = d * INV_T;
}

// ---------------------------------------------------------------------------
// 4) Finalize: loss = mean_p [ log(exp(S_p) + neg_sum) - S_p ]
// ---------------------------------------------------------------------------
__global__ void final_kernel(float* __restrict__ out) {
    int tid = threadIdx.x;
    float negf = (float)g_neg;
    float s = 0.0f;
    for (int p = tid; p < NPAIRS; p += 256) {
        float sp = g_pos[p];
        s += logf(__expf(sp) + negf) - sp;
    }
    #pragma unroll
    for (int off = 16; off > 0; off >>= 1)
        s += __shfl_down_sync(0xffffffffu, s, off);
    __shared__ float red[8];
    if ((tid & 31) == 0) red[tid >> 5] = s;
    __syncthreads();
    if (tid == 0) {
        float t = 0.0f;
        #pragma unroll
        for (int w = 0; w < 8; w++) t += red[w];
        out[0] = t / (float)NPAIRS;
    }
}

// ---------------------------------------------------------------------------
extern "C" void kernel_launch(void* const* d_in, const int* in_sizes, int n_in,
                              void* d_out, int out_size) {
    const float* E      = (const float*)d_in[0];
    const int*   labels = (const int*)d_in[1];
    float*       out    = (float*)d_out;

    normalize_kernel<<<TOTAL, 128>>>(E);

    dim3 grid(TOTAL / BN, TOTAL / BM);   // 32 x 32; lower-triangle blocks early-exit
    gemm_negsum_kernel<<<grid, 256>>>(labels);

    pos_kernel<<<(NPAIRS * 32) / 256, 256>>>();
    final_kernel<<<1, 256>>>(out);
}

// round 3
// speedup vs baseline: 3.1912x; 3.1912x over previous
#include <cuda_runtime.h>
#include <cuda_bf16.h>
#include <cstdint>
#include <math.h>

// ---------------- problem constants ----------------
#define TOTAL    4096
#define DDIM     512
#define NPAIRS   2048
#define KAUG     576          // 512 dims + 64 label one-hot dims
#define NT       32           // 4096/128 tile grid
#define NTILES   528          // NT*(NT+1)/2 upper-triangular tiles
#define BT       128
#define KCHUNK   64           // bf16 elems per K chunk (128 bytes per smem row)
#define NCHUNKS  9            // 576 / 64
#define INV_T    (1.0f/0.07f)
// sqrt( (1/0.07) * log2(e) ): both operands pre-scaled so accumulator is log2-units
#define SCALE_LOG2 4.539816f

// ---------------- device scratch ----------------
__device__ __nv_bfloat16 g_row[TOTAL * KAUG];  // scaled + (+16)*onehot(label)
__device__ __nv_bfloat16 g_col[TOTAL * KAUG];  // scaled + (-8)*onehot(label)
__device__ float  g_pos[NPAIRS];
__device__ double g_neg;

// ---------------- small asm helpers (all sm_80-era PTX) ----------------
__device__ __forceinline__ uint32_t smem_u32(const void* p) {
    return (uint32_t)__cvta_generic_to_shared(p);
}
__device__ __forceinline__ void ldmatrix_x4(uint32_t* r, uint32_t addr) {
    asm volatile("ldmatrix.sync.aligned.m8n8.x4.shared.b16 {%0,%1,%2,%3}, [%4];"
        : "=r"(r[0]), "=r"(r[1]), "=r"(r[2]), "=r"(r[3]) : "r"(addr));
}
__device__ __forceinline__ void mma16816(float* c, const uint32_t* a,
                                         uint32_t b0, uint32_t b1) {
    asm volatile(
        "mma.sync.aligned.m16n8k16.row.col.f32.bf16.bf16.f32 "
        "{%0,%1,%2,%3}, {%4,%5,%6,%7}, {%8,%9}, {%0,%1,%2,%3};"
        : "+f"(c[0]), "+f"(c[1]), "+f"(c[2]), "+f"(c[3])
        : "r"(a[0]), "r"(a[1]), "r"(a[2]), "r"(a[3]), "r"(b0), "r"(b1));
}
#define CP_ASYNC16(so, gp) \
    asm volatile("cp.async.cg.shared.global [%0], [%1], 16;" :: "r"(so), "l"(gp))
#define CP_COMMIT()  asm volatile("cp.async.commit_group;" ::: "memory")
#define CP_WAIT(n)   asm volatile("cp.async.wait_group %0;" :: "n"(n) : "memory")

// ---------------------------------------------------------------------------
// 1) prep: L2-normalize rows, scale by sqrt(log2e/T), cast bf16, append label
//    one-hot block (+16 row side, -8 col side => -128 in the accumulator when
//    labels match). One block of 128 threads per row.
// ---------------------------------------------------------------------------
__global__ void prep_kernel(const float* __restrict__ E, const int* __restrict__ labels) {
    int row = blockIdx.x;
    int tid = threadIdx.x;
    if (row == 0 && tid == 0) g_neg = 0.0;

    float4 v = reinterpret_cast<const float4*>(E + (size_t)row * DDIM)[tid];
    float ss = v.x * v.x + v.y * v.y + v.z * v.z + v.w * v.w;
    #pragma unroll
    for (int off = 16; off > 0; off >>= 1) ss += __shfl_down_sync(0xffffffffu, ss, off);
    __shared__ float ws[4];
    if ((tid & 31) == 0) ws[tid >> 5] = ss;
    __syncthreads();
    float s = rsqrtf(ws[0] + ws[1] + ws[2] + ws[3]) * SCALE_LOG2;

    __nv_bfloat16* rw = g_row + (size_t)row * KAUG + tid * 4;
    __nv_bfloat16* cw = g_col + (size_t)row * KAUG + tid * 4;
    rw[0] = cw[0] = __float2bfloat16(v.x * s);
    rw[1] = cw[1] = __float2bfloat16(v.y * s);
    rw[2] = cw[2] = __float2bfloat16(v.z * s);
    rw[3] = cw[3] = __float2bfloat16(v.w * s);

    if (tid < 64) {
        int lab = labels[row >> 1];
        g_row[(size_t)row * KAUG + DDIM + tid] = __float2bfloat16(tid == lab ? 16.0f : 0.0f);
        g_col[(size_t)row * KAUG + DDIM + tid] = __float2bfloat16(tid == lab ? -8.0f : 0.0f);
    }
}

// ---------------------------------------------------------------------------
// 2) HMMA (mma.sync bf16) GEMM over upper-triangular tiles, fused exp2-sum
//    epilogue on the register accumulators. 128x128 CTA tile, 8 warps, each
//    warp 64x32. K pipelined in 64-elem chunks via cp.async double buffering.
//    smem rows are 128B with SW128-style xor swizzle for conflict-free ldmatrix.
// ---------------------------------------------------------------------------
__device__ __forceinline__ void load_chunk(uint32_t sb, int tid, int row0, int col0,
                                           int c, int buf) {
    #pragma unroll
    for (int itv = 0; itv < 8; itv++) {
        int slot = itv * 256 + tid;           // 0..2047 16B transfers
        int isB  = slot >> 10;
        int s2   = slot & 1023;
        int r    = s2 >> 3;                   // row in tile (0..127)
        int g    = s2 & 7;                    // 16B group in 128B row
        const __nv_bfloat16* src = isB
            ? (g_col + (size_t)(col0 + r) * KAUG)
            : (g_row + (size_t)(row0 + r) * KAUG);
        src += c * KCHUNK + g * 8;
        uint32_t so = sb + buf * 32768 + isB * 16384
                    + (uint32_t)(r * 128) + (uint32_t)((g * 16) ^ ((r & 7) * 16));
        CP_ASYNC16(so, src);
    }
    CP_COMMIT();
}

__global__ void __launch_bounds__(256, 2) gemm_negsum_kernel() {
    extern __shared__ char smem[];
    __shared__ float red[8];
    uint32_t sb = smem_u32(smem);

    int tid  = threadIdx.x;
    int lane = tid & 31;
    int wid  = tid >> 5;

    // triangular tile decode
    int t = blockIdx.x, bi = 0, rem = NT;
    while (t >= rem) { t -= rem; rem--; bi++; }
    int bj = bi + t;
    int row0 = bi * BT, col0 = bj * BT;

    load_chunk(sb, tid, row0, col0, 0, 0);
    load_chunk(sb, tid, row0, col0, 1, 1);

    // warp tile: 64 (m) x 32 (n)
    int wm0 = (wid & 1) * 64;
    int wn0 = (wid >> 1) * 32;

    // ldmatrix lane addressing (swizzle xor is row%8-invariant under +16 rows)
    int arow = wm0 + (lane & 15);
    uint32_t a_xor = (uint32_t)((arow & 7) * 16);
    uint32_t a_colbase = (uint32_t)((lane >> 4) * 16);
    int brow = wn0 + ((lane >> 4) & 1) * 8 + (lane & 7);
    uint32_t b_xor = (uint32_t)((brow & 7) * 16);
    uint32_t b_colbase = (uint32_t)(((lane >> 3) & 1) * 16);

    float acc[4][4][4];
    #pragma unroll
    for (int i = 0; i < 4; i++)
        #pragma unroll
        for (int j = 0; j < 4; j++)
            #pragma unroll
            for (int e = 0; e < 4; e++) acc[i][j][e] = 0.0f;

    for (int c = 0; c < NCHUNKS; c++) {
        int buf = c & 1;
        if (c == NCHUNKS - 1) { CP_WAIT(0); } else { CP_WAIT(1); }
        __syncthreads();

        uint32_t Ab = sb + (uint32_t)(buf * 32768);
        uint32_t Bb = Ab + 16384;
        #pragma unroll
        for (int ks = 0; ks < 4; ks++) {
            uint32_t a[4][4];
            uint32_t acol = (uint32_t)(ks * 32) + a_colbase;
            #pragma unroll
            for (int mt = 0; mt < 4; mt++)
                ldmatrix_x4(a[mt], Ab + (uint32_t)((arow + mt * 16) * 128) + (acol ^ a_xor));

            uint32_t b[2][4];
            uint32_t bcol = (uint32_t)(ks * 32) + b_colbase;
            #pragma unroll
            for (int p = 0; p < 2; p++)
                ldmatrix_x4(b[p], Bb + (uint32_t)((brow + p * 16) * 128) + (bcol ^ b_xor));

            #pragma unroll
            for (int mt = 0; mt < 4; mt++)
                #pragma unroll
                for (int nt = 0; nt < 4; nt++)
                    mma16816(acc[mt][nt], a[mt],
                             b[nt >> 1][(nt & 1) * 2 + 0],
                             b[nt >> 1][(nt & 1) * 2 + 1]);
        }
        __syncthreads();
        if (c + 2 < NCHUNKS) load_chunk(sb, tid, row0, col0, c + 2, buf);
    }

    // ---- epilogue: exp2 over all 64 register accumulators ----
    float lsum = 0.0f;
    #pragma unroll
    for (int mt = 0; mt < 4; mt++)
        #pragma unroll
        for (int nt = 0; nt < 4; nt++)
            #pragma unroll
            for (int e = 0; e < 4; e++) {
                float tv = acc[mt][nt][e];          // log2-units; masked ~= -107
                tv = fmaxf(tv, -100.0f);
                float rr = tv + 12582912.0f;        // round-to-nearest-int magic
                float kf = rr - 12582912.0f;
                float f  = tv - kf;                 // f in [-0.5, 0.5]
                float p  = fmaf(f, 0.009618129f, 0.05550411f);
                p = fmaf(f, p, 0.24022651f);
                p = fmaf(f, p, 0.69314718f);
                p = fmaf(f, p, 1.0f);               // ~= 2^f
                lsum += __int_as_float((__float_as_int(rr) << 23) + __float_as_int(p));
            }
    if (bi == bj) lsum *= 0.5f;                     // diagonal tile counts pairs twice

    #pragma unroll
    for (int off = 16; off > 0; off >>= 1) lsum += __shfl_down_sync(0xffffffffu, lsum, off);
    if (lane == 0) red[wid] = lsum;
    __syncthreads();
    if (tid == 0) {
        float s = 0.0f;
        #pragma unroll
        for (int w = 0; w < 8; w++) s += red[w];
        atomicAdd(&g_neg, (double)s);
    }
}

// ---------------------------------------------------------------------------
// 3) positive-pair logits in fp32 straight from E (normalize on the fly)
// ---------------------------------------------------------------------------
__global__ void pos_kernel(const float* __restrict__ E) {
    int pair = (blockIdx.x * blockDim.x + threadIdx.x) >> 5;
    int lane = threadIdx.x & 31;
    const float4* a = reinterpret_cast<const float4*>(E + (size_t)(2 * pair) * DDIM);
    const float4* b = a + DDIM / 4;
    float aa = 0.f, bb = 0.f, ab = 0.f;
    #pragma unroll
    for (int i = lane; i < DDIM / 4; i += 32) {
        float4 x = a[i], y = b[i];
        aa += x.x * x.x + x.y * x.y + x.z * x.z + x.w * x.w;
        bb += y.x * y.x + y.y * y.y + y.z * y.z + y.w * y.w;
        ab += x.x * y.x + x.y * y.y + x.z * y.z + x.w * y.w;
    }
    #pragma unroll
    for (int off = 16; off > 0; off >>= 1) {
        aa += __shfl_down_sync(0xffffffffu, aa, off);
        bb += __shfl_down_sync(0xffffffffu, bb, off);
        ab += __shfl_down_sync(0xffffffffu, ab, off);
    }
    if (lane == 0) g_pos[pair] = ab * rsqrtf(aa * bb) * INV_T;
}

// ---------------------------------------------------------------------------
// 4) finalize: loss = mean_p [ log(exp(S_p) + neg_sum) - S_p ]
// ---------------------------------------------------------------------------
__global__ void final_kernel(float* __restrict__ out) {
    int tid = threadIdx.x;
    float negf = (float)g_neg;
    float s = 0.0f;
    for (int p = tid; p < NPAIRS; p += 256) {
        float sp = g_pos[p];
        s += __logf(__expf(sp) + negf) - sp;
    }
    #pragma unroll
    for (int off = 16; off > 0; off >>= 1) s += __shfl_down_sync(0xffffffffu, s, off);
    __shared__ float red[8];
    if ((tid & 31) == 0) red[tid >> 5] = s;
    __syncthreads();
    if (tid == 0) {
        float tot = 0.0f;
        #pragma unroll
        for (int w = 0; w < 8; w++) tot += red[w];
        out[0] = tot / (float)NPAIRS;
    }
}

// ---------------------------------------------------------------------------
extern "C" void kernel_launch(void* const* d_in, const int* in_sizes, int n_in,
                              void* d_out, int out_size) {
    const float* E      = (const float*)d_in[0];
    const int*   labels = (const int*)d_in[1];
    float*       out    = (float*)d_out;

    const int SMEM_BYTES = 2 * 32768;   // double-buffered A+B tiles
    cudaFuncSetAttribute(gemm_negsum_kernel,
                         cudaFuncAttributeMaxDynamicSharedMemorySize, SMEM_BYTES);

    prep_kernel<<<TOTAL, 128>>>(E, labels);
    gemm_negsum_kernel<<<NTILES, 256, SMEM_BYTES>>>();
    pos_kernel<<<(NPAIRS * 32) / 256, 256>>>(E);
    final_kernel<<<1, 256>>>(out);
}

// round 5
// speedup vs baseline: 5.4306x; 1.7018x over previous
#include <cuda_runtime.h>
#include <cuda_fp16.h>
#include <cstdint>
#include <math.h>

// ---------------- problem constants ----------------
#define TOTAL    4096
#define DDIM     512
#define NPAIRS   2048
#define KAUG     576          // 512 dims + 64 label one-hot dims
#define NT       32           // 4096/128 tile grid
#define NTILES   528          // NT*(NT+1)/2 upper-triangular tiles
#define BT       128
#define KCHUNK   64           // f16 elems per K chunk (128 bytes per smem row)
#define NCHUNKS  9            // 576 / 64
#define INV_T    (1.0f/0.07f)
// sqrt( (1/0.07) * log2(e) ): operands pre-scaled so accumulator is log2-units
#define SCALE_LOG2 4.539816f

// ---------------- device scratch ----------------
__device__ __half g_row[TOTAL * KAUG];  // scaled + (+16)*onehot(label)
__device__ __half g_col[TOTAL * KAUG];  // scaled + (-8)*onehot(label)
__device__ float  g_pos[NPAIRS];
__device__ double g_neg;
__device__ int    g_cnt;

// ---------------- asm helpers (sm_80-era PTX only) ----------------
__device__ __forceinline__ uint32_t smem_u32(const void* p) {
    return (uint32_t)__cvta_generic_to_shared(p);
}
__device__ __forceinline__ uint32_t h2_bits(__half2 h) {
    return *reinterpret_cast<uint32_t*>(&h);
}
__device__ __forceinline__ void ldmatrix_x4(uint32_t* r, uint32_t addr) {
    asm volatile("ldmatrix.sync.aligned.m8n8.x4.shared.b16 {%0,%1,%2,%3}, [%4];"
        : "=r"(r[0]), "=r"(r[1]), "=r"(r[2]), "=r"(r[3]) : "r"(addr));
}
// f16 accumulate: D (2x f16x2 regs) = A(4) * B(2) + D
__device__ __forceinline__ void mma16816_f16(uint32_t* c, const uint32_t* a,
                                             uint32_t b0, uint32_t b1) {
    asm volatile(
        "mma.sync.aligned.m16n8k16.row.col.f16.f16.f16.f16 "
        "{%0,%1}, {%2,%3,%4,%5}, {%6,%7}, {%0,%1};"
        : "+r"(c[0]), "+r"(c[1])
        : "r"(a[0]), "r"(a[1]), "r"(a[2]), "r"(a[3]), "r"(b0), "r"(b1));
}
#define CP_ASYNC16(so, gp) \
    asm volatile("cp.async.cg.shared.global [%0], [%1], 16;" :: "r"(so), "l"(gp))
#define CP_COMMIT()  asm volatile("cp.async.commit_group;" ::: "memory")
#define CP_WAIT(n)   asm volatile("cp.async.wait_group %0;" :: "n"(n) : "memory")

// fast exp2 on log2-unit accumulators (masked lanes ~ -107, clamped to -100)
__device__ __forceinline__ float exp2_fast(float tv) {
    tv = fmaxf(tv, -100.0f);
    float rr = tv + 12582912.0f;            // round-to-nearest-int magic (1.5*2^23)
    float kf = rr - 12582912.0f;
    float f  = tv - kf;                     // f in [-0.5, 0.5]
    float p  = fmaf(f, 0.009618129f, 0.05550411f);
    p = fmaf(f, p, 0.24022651f);
    p = fmaf(f, p, 0.69314718f);
    p = fmaf(f, p, 1.0f);                   // ~= 2^f
    return __int_as_float((__float_as_int(rr) << 23) + __float_as_int(p));
}

// ---------------------------------------------------------------------------
// 1) prep+pos: one block per augmentation pair (rows 2p, 2p+1).
//    L2-normalize both rows, scale by sqrt(log2e/T), cast f16, append label
//    one-hot block (+16 row side, -8 col side => -128 in accumulator when
//    labels match). Also computes the positive-pair logit in fp32.
// ---------------------------------------------------------------------------
__global__ void prep_kernel(const float* __restrict__ E, const int* __restrict__ labels) {
    int pair = blockIdx.x;
    int tid  = threadIdx.x;       // 128 threads
    int lane = tid & 31, wid = tid >> 5;

    const float4* A = reinterpret_cast<const float4*>(E + (size_t)(2 * pair) * DDIM);
    const float4* B = A + DDIM / 4;
    float4 a = A[tid], b = B[tid];
    float aa = a.x*a.x + a.y*a.y + a.z*a.z + a.w*a.w;
    float bb = b.x*b.x + b.y*b.y + b.z*b.z + b.w*b.w;
    float ab = a.x*b.x + a.y*b.y + a.z*b.z + a.w*b.w;
    #pragma unroll
    for (int off = 16; off > 0; off >>= 1) {
        aa += __shfl_down_sync(0xffffffffu, aa, off);
        bb += __shfl_down_sync(0xffffffffu, bb, off);
        ab += __shfl_down_sync(0xffffffffu, ab, off);
    }
    __shared__ float s_aa[4], s_bb[4], s_ab[4];
    if (lane == 0) { s_aa[wid] = aa; s_bb[wid] = bb; s_ab[wid] = ab; }
    __syncthreads();
    float taa = s_aa[0] + s_aa[1] + s_aa[2] + s_aa[3];
    float tbb = s_bb[0] + s_bb[1] + s_bb[2] + s_bb[3];
    float tab = s_ab[0] + s_ab[1] + s_ab[2] + s_ab[3];
    float sa = rsqrtf(taa) * SCALE_LOG2;
    float sb = rsqrtf(tbb) * SCALE_LOG2;

    size_t baseA = (size_t)(2 * pair) * KAUG + tid * 4;
    size_t baseB = baseA + KAUG;
    uint2 pa, pb;
    pa.x = h2_bits(__floats2half2_rn(a.x * sa, a.y * sa));
    pa.y = h2_bits(__floats2half2_rn(a.z * sa, a.w * sa));
    pb.x = h2_bits(__floats2half2_rn(b.x * sb, b.y * sb));
    pb.y = h2_bits(__floats2half2_rn(b.z * sb, b.w * sb));
    *reinterpret_cast<uint2*>(g_row + baseA) = pa;
    *reinterpret_cast<uint2*>(g_col + baseA) = pa;
    *reinterpret_cast<uint2*>(g_row + baseB) = pb;
    *reinterpret_cast<uint2*>(g_col + baseB) = pb;

    if (tid < 64) {
        int lab = labels[pair];
        __half hr = __float2half(tid == lab ? 16.0f : 0.0f);
        __half hc = __float2half(tid == lab ? -8.0f : 0.0f);
        size_t oA = (size_t)(2 * pair) * KAUG + DDIM + tid;
        g_row[oA] = hr;          g_col[oA] = hc;
        g_row[oA + KAUG] = hr;   g_col[oA + KAUG] = hc;
    }
    if (tid == 0) {
        g_pos[pair] = tab * rsqrtf(taa * tbb) * INV_T;
        if (pair == 0) { g_neg = 0.0; g_cnt = 0; }
    }
}

// ---------------------------------------------------------------------------
// 2) HMMA f16-acc GEMM over upper-triangular tiles + fused exp2-sum epilogue.
//    128x128 CTA tile, 4 warps, each 64x64. cp.async double buffering.
//    Last CTA to finish computes the final loss (counter pattern).
// ---------------------------------------------------------------------------
__device__ __forceinline__ void load_chunk(uint32_t sb, int tid, int row0, int col0,
                                           int c, int buf) {
    #pragma unroll
    for (int itv = 0; itv < 16; itv++) {
        int slot = itv * 128 + tid;           // 0..2047 16B transfers
        int isB  = slot >> 10;
        int s2   = slot & 1023;
        int r    = s2 >> 3;                   // row in tile (0..127)
        int g    = s2 & 7;                    // 16B group in 128B row
        const __half* src = isB
            ? (g_col + (size_t)(col0 + r) * KAUG)
            : (g_row + (size_t)(row0 + r) * KAUG);
        src += c * KCHUNK + g * 8;
        uint32_t so = sb + buf * 32768 + isB * 16384
                    + (uint32_t)(r * 128) + (uint32_t)((g * 16) ^ ((r & 7) * 16));
        CP_ASYNC16(so, src);
    }
    CP_COMMIT();
}

__global__ void __launch_bounds__(128, 3) gemm_negsum_kernel(float* __restrict__ out) {
    extern __shared__ char smem[];
    __shared__ float red[4];
    __shared__ int   lastflag;
    uint32_t sb = smem_u32(smem);

    int tid  = threadIdx.x;
    int lane = tid & 31;
    int wid  = tid >> 5;

    // triangular tile decode
    int t = blockIdx.x, bi = 0, rem = NT;
    while (t >= rem) { t -= rem; rem--; bi++; }
    int bj = bi + t;
    int row0 = bi * BT, col0 = bj * BT;

    load_chunk(sb, tid, row0, col0, 0, 0);
    load_chunk(sb, tid, row0, col0, 1, 1);

    // warp tile: 64 (m) x 64 (n)
    int wm0 = (wid & 1) * 64;
    int wn0 = (wid >> 1) * 64;

    int arow = wm0 + (lane & 15);
    uint32_t a_xor = (uint32_t)((arow & 7) * 16);
    uint32_t a_colbase = (uint32_t)((lane >> 4) * 16);
    int brow = wn0 + ((lane >> 4) & 1) * 8 + (lane & 7);
    uint32_t b_xor = (uint32_t)((brow & 7) * 16);
    uint32_t b_colbase = (uint32_t)(((lane >> 3) & 1) * 16);

    uint32_t acc[4][8][2];                    // f16x2 accumulators
    #pragma unroll
    for (int i = 0; i < 4; i++)
        #pragma unroll
        for (int j = 0; j < 8; j++) { acc[i][j][0] = 0u; acc[i][j][1] = 0u; }

    for (int c = 0; c < NCHUNKS; c++) {
        int buf = c & 1;
        if (c == NCHUNKS - 1) { CP_WAIT(0); } else { CP_WAIT(1); }
        __syncthreads();

        uint32_t Ab = sb + (uint32_t)(buf * 32768);
        uint32_t Bb = Ab + 16384;
        #pragma unroll
        for (int ks = 0; ks < 4; ks++) {
            uint32_t a[4][4];
            uint32_t acol = (uint32_t)(ks * 32) + a_colbase;
            #pragma unroll
            for (int mt = 0; mt < 4; mt++)
                ldmatrix_x4(a[mt], Ab + (uint32_t)((arow + mt * 16) * 128) + (acol ^ a_xor));

            uint32_t b[4][4];
            uint32_t bcol = (uint32_t)(ks * 32) + b_colbase;
            #pragma unroll
            for (int p = 0; p < 4; p++)
                ldmatrix_x4(b[p], Bb + (uint32_t)((brow + p * 16) * 128) + (bcol ^ b_xor));

            #pragma unroll
            for (int mt = 0; mt < 4; mt++)
                #pragma unroll
                for (int nt = 0; nt < 8; nt++)
                    mma16816_f16(acc[mt][nt], a[mt],
                                 b[nt >> 1][(nt & 1) * 2 + 0],
                                 b[nt >> 1][(nt & 1) * 2 + 1]);
        }
        __syncthreads();
        if (c + 2 < NCHUNKS) load_chunk(sb, tid, row0, col0, c + 2, buf);
    }

    // ---- epilogue: exp2 over all 128 f16 accumulators ----
    float lsum = 0.0f;
    #pragma unroll
    for (int mt = 0; mt < 4; mt++)
        #pragma unroll
        for (int nt = 0; nt < 8; nt++)
            #pragma unroll
            for (int e = 0; e < 2; e++) {
                float2 v = __half22float2(*reinterpret_cast<__half2*>(&acc[mt][nt][e]));
                lsum += exp2_fast(v.x);
                lsum += exp2_fast(v.y);
            }
    if (bi == bj) lsum *= 0.5f;               // diagonal tile counts pairs twice

    #pragma unroll
    for (int off = 16; off > 0; off >>= 1) lsum += __shfl_down_sync(0xffffffffu, lsum, off);
    if (lane == 0) red[wid] = lsum;
    __syncthreads();
    if (tid == 0) {
        atomicAdd(&g_neg, (double)(red[0] + red[1] + red[2] + red[3]));
        __threadfence();
        lastflag = (atomicAdd(&g_cnt, 1) == NTILES - 1);
    }
    __syncthreads();

    // ---- last CTA computes the final loss ----
    if (lastflag) {
        __threadfence();
        float negf = (float)g_neg;
        float s = 0.0f;
        for (int p = tid; p < NPAIRS; p += 128) {
            float sp = g_pos[p];
            s += __logf(__expf(sp) + negf) - sp;
        }
        #pragma unroll
        for (int off = 16; off > 0; off >>= 1) s += __shfl_down_sync(0xffffffffu, s, off);
        if (lane == 0) red[wid] = s;
        __syncthreads();
        if (tid == 0) {
            out[0] = (red[0] + red[1] + red[2] + red[3]) / (float)NPAIRS;
            g_cnt = 0;
        }
    }
}

// ---------------------------------------------------------------------------
extern "C" void kernel_launch(void* const* d_in, const int* in_sizes, int n_in,
                              void* d_out, int out_size) {
    const float* E      = (const float*)d_in[0];
    const int*   labels = (const int*)d_in[1];
    float*       out    = (float*)d_out;

    const int SMEM_BYTES = 2 * 32768;   // double-buffered A+B tiles
    cudaFuncSetAttribute(gemm_negsum_kernel,
                         cudaFuncAttributeMaxDynamicSharedMemorySize, SMEM_BYTES);

    prep_kernel<<<NPAIRS, 128>>>(E, labels);
    gemm_negsum_kernel<<<NTILES, 128, SMEM_BYTES>>>(out);
}